// round 6
// baseline (speedup 1.0000x reference)
#include <cuda_runtime.h>
#include <cuda_bf16.h>
#include <math.h>
#include <stdint.h>

#define BB 4
#define NN 1024
#define DD 768
#define HH 12
#define HD 64
#define MROWS (BB*NN)          // 4096
#define KDIM 768
#define KCHUNK 32
#define NCHUNKS (KDIM/KCHUNK)  // 24

// ---------------- scratch (no allocations allowed) ----------------
__device__ __nv_bfloat16 g_qh[BB*HH*NN*HD];
__device__ __nv_bfloat16 g_ql[BB*HH*NN*HD];
__device__ __nv_bfloat16 g_kh[BB*HH*NN*HD];
__device__ __nv_bfloat16 g_kl[BB*HH*NN*HD];
__device__ __nv_bfloat16 g_vh[BB*HH*NN*HD];
__device__ __nv_bfloat16 g_vl[BB*HH*NN*HD];
__device__ __nv_bfloat16 g_xh[MROWS*KDIM];
__device__ __nv_bfloat16 g_xl[MROWS*KDIM];
__device__ __nv_bfloat16 g_wqh[3*DD*KDIM];
__device__ __nv_bfloat16 g_wql[3*DD*KDIM];
__device__ __nv_bfloat16 g_wph[DD*KDIM];
__device__ __nv_bfloat16 g_wpl[DD*KDIM];
__device__ __nv_bfloat16 g_atth[BB*NN*DD];
__device__ __nv_bfloat16 g_attl[BB*NN*DD];
__device__ int   g_cx[BB*NN];
__device__ int   g_cy[BB*NN];

// ---------------- helpers ----------------
__device__ __forceinline__ uint32_t smem_u32(const void* p) {
    uint32_t a;
    asm("{ .reg .u64 t; cvta.to.shared.u64 t, %1; cvt.u32.u64 %0, t; }" : "=r"(a) : "l"(p));
    return a;
}

#define LDSM_X4(r0, r1, r2, r3, addr) \
    asm volatile("ldmatrix.sync.aligned.m8n8.x4.shared.b16 {%0,%1,%2,%3}, [%4];" \
        : "=r"(r0), "=r"(r1), "=r"(r2), "=r"(r3) : "r"(addr))

#define LDSM_X4_T(r0, r1, r2, r3, addr) \
    asm volatile("ldmatrix.sync.aligned.m8n8.x4.trans.shared.b16 {%0,%1,%2,%3}, [%4];" \
        : "=r"(r0), "=r"(r1), "=r"(r2), "=r"(r3) : "r"(addr))

#define MMA16816(d, a0, a1, a2, a3, b0, b1) \
    asm volatile("mma.sync.aligned.m16n8k16.row.col.f32.bf16.bf16.f32 " \
        "{%0,%1,%2,%3}, {%4,%5,%6,%7}, {%8,%9}, {%0,%1,%2,%3};" \
        : "+f"((d)[0]), "+f"((d)[1]), "+f"((d)[2]), "+f"((d)[3]) \
        : "r"(a0), "r"(a1), "r"(a2), "r"(a3), "r"(b0), "r"(b1))

#define CP_ASYNC16(dst, src) \
    asm volatile("cp.async.cg.shared.global [%0], [%1], 16;" :: "r"(dst), "l"(src) : "memory")
#define CP_COMMIT() asm volatile("cp.async.commit_group;" ::: "memory")
#define CP_WAIT(n)  asm volatile("cp.async.wait_group %0;" :: "n"(n) : "memory")

// SW128 swizzled address within a [rows][128 bytes] tile
__device__ __forceinline__ uint32_t swz(uint32_t base, int row, int colb) {
    uint32_t off = (uint32_t)(row * 128 + colb);
    return base + (off ^ ((off >> 3) & 0x70));
}
// SW64 swizzled address within a [rows][64 bytes] tile
__device__ __forceinline__ uint32_t swz64(uint32_t base, int row, int colb) {
    uint32_t off = (uint32_t)(row * 64 + colb);
    return base + (off ^ ((off >> 3) & 0x30));
}

// fp32 -> bf16 hi/lo split of a float4 (packed as 2x bf16x2 each)
__device__ __forceinline__ void split4(float4 f, uint2& hi, uint2& lo) {
    __nv_bfloat16 hx = __float2bfloat16_rn(f.x);
    __nv_bfloat16 hy = __float2bfloat16_rn(f.y);
    __nv_bfloat16 hz = __float2bfloat16_rn(f.z);
    __nv_bfloat16 hw = __float2bfloat16_rn(f.w);
    __nv_bfloat162 h01; h01.x = hx; h01.y = hy;
    __nv_bfloat162 h23; h23.x = hz; h23.y = hw;
    hi.x = *(uint32_t*)&h01; hi.y = *(uint32_t*)&h23;
    __nv_bfloat162 l01 = __floats2bfloat162_rn(f.x - __bfloat162float(hx), f.y - __bfloat162float(hy));
    __nv_bfloat162 l23 = __floats2bfloat162_rn(f.z - __bfloat162float(hz), f.w - __bfloat162float(hw));
    lo.x = *(uint32_t*)&l01; lo.y = *(uint32_t*)&l23;
}

__device__ __forceinline__ uint32_t pack_hi(float a, float b) {
    __nv_bfloat162 h = __floats2bfloat162_rn(a, b);
    return *(uint32_t*)&h;
}
__device__ __forceinline__ uint32_t pack_lo(float a, float b) {
    __nv_bfloat16 ha = __float2bfloat16_rn(a);
    __nv_bfloat16 hb = __float2bfloat16_rn(b);
    __nv_bfloat162 l = __floats2bfloat162_rn(a - __bfloat162float(ha), b - __bfloat162float(hb));
    return *(uint32_t*)&l;
}

// ---------------- prep: integer grid coords ----------------
__global__ void prep_kernel(const float* __restrict__ coords) {
    int i = blockIdx.x * blockDim.x + threadIdx.x;
    if (i < BB*NN) {
        g_cx[i] = (int)(coords[2*i + 0] * 128.0f);
        g_cy[i] = (int)(coords[2*i + 1] * 128.0f);
    }
}

// ---------------- split: fp32 -> bf16 hi/lo ----------------
__global__ void split_kernel(const float* __restrict__ src,
                             __nv_bfloat16* __restrict__ h,
                             __nv_bfloat16* __restrict__ l, int n) {
    int i = (blockIdx.x * blockDim.x + threadIdx.x) * 4;
    if (i < n) {
        float4 f = *(const float4*)(src + i);
        uint2 hh, ll;
        split4(f, hh, ll);
        *(uint2*)(h + i) = hh;
        *(uint2*)(l + i) = ll;
    }
}

// ---------------- HMMA bf16x3 GEMM, cp.async 3-stage pipeline, 2 CTAs/SM ----------------
// C[M,N] = A[M,K].B[N,K]^T + bias.  A,B pre-split bf16 hi/lo. KCHUNK=32.
#define GSTAGES 3
#define GSTAGE_BYTES 32768                  // Ahi 8K | Alo 8K | Bhi 8K | Blo 8K (SW64)
#define GEMM_SMEM (GSTAGES*GSTAGE_BYTES)    // 96KB -> 2 CTAs/SM

__device__ __forceinline__ void gemm_load_stage(uint32_t sbase,
    const __nv_bfloat16* __restrict__ Ah, const __nv_bfloat16* __restrict__ Al,
    const __nv_bfloat16* __restrict__ Bh, const __nv_bfloat16* __restrict__ Bl,
    int row0, int col0, int kt0, int tid) {
#pragma unroll
    for (int i = 0; i < 2; i++) {
        int c = i*256 + tid;              // 0..511
        int row = c >> 2, c16 = c & 3;    // 128 rows x 4 x 16B
        uint32_t off = (uint32_t)(row*64 + c16*16);
        uint32_t sw = off ^ ((off >> 3) & 0x30);
        size_t ga = (size_t)(row0 + row)*KDIM + kt0 + c16*8;
        size_t gb = (size_t)(col0 + row)*KDIM + kt0 + c16*8;
        CP_ASYNC16(sbase + sw,         Ah + ga);
        CP_ASYNC16(sbase + 8192  + sw, Al + ga);
        CP_ASYNC16(sbase + 16384 + sw, Bh + gb);
        CP_ASYNC16(sbase + 24576 + sw, Bl + gb);
    }
}

template<int MODE>
__global__ __launch_bounds__(256, 2) void mma_gemm(
        const __nv_bfloat16* __restrict__ Ah, const __nv_bfloat16* __restrict__ Al,
        const __nv_bfloat16* __restrict__ Bh, const __nv_bfloat16* __restrict__ Bl,
        const float* __restrict__ bias, float* __restrict__ Cout) {
    extern __shared__ char smem[];
    uint32_t sb = smem_u32(smem);

    const int tid = threadIdx.x;
    const int wid = tid >> 5;
    const int lane = tid & 31;
    const int warp_m = wid >> 2;
    const int warp_n = wid & 3;
    const int row0 = blockIdx.y * 128;
    const int col0 = blockIdx.x * 128;

    float acc[4][4][4];
#pragma unroll
    for (int i = 0; i < 4; i++)
#pragma unroll
        for (int j = 0; j < 4; j++)
#pragma unroll
            for (int r = 0; r < 4; r++) acc[i][j][r] = 0.0f;

    // prologue: stages 0,1
    gemm_load_stage(sb, Ah, Al, Bh, Bl, row0, col0, 0, tid);
    CP_COMMIT();
    gemm_load_stage(sb + GSTAGE_BYTES, Ah, Al, Bh, Bl, row0, col0, KCHUNK, tid);
    CP_COMMIT();

    for (int ch = 0; ch < NCHUNKS; ch++) {
        if (ch < NCHUNKS-1) CP_WAIT(1); else CP_WAIT(0);
        __syncthreads();   // stage ch ready AND all warps done computing ch-1
        if (ch + 2 < NCHUNKS) {
            gemm_load_stage(sb + ((ch+2)%GSTAGES)*GSTAGE_BYTES, Ah, Al, Bh, Bl,
                            row0, col0, (ch+2)*KCHUNK, tid);
            CP_COMMIT();
        }

        const uint32_t st = sb + (ch % GSTAGES)*GSTAGE_BYTES;
        const uint32_t sAhi = st, sAlo = st + 8192, sBhi = st + 16384, sBlo = st + 24576;
#pragma unroll
        for (int ks = 0; ks < 2; ks++) {
            uint32_t bh[4][2], bl[4][2];
#pragma unroll
            for (int g = 0; g < 2; g++) {
                int brow = warp_n*32 + g*16 + (lane & 15);
                int bcol = ks*32 + ((lane >> 4) << 4);
                uint32_t r0, r1, r2, r3;
                LDSM_X4(r0, r1, r2, r3, swz64(sBhi, brow, bcol));
                bh[g*2+0][0] = r0; bh[g*2+1][0] = r1;
                bh[g*2+0][1] = r2; bh[g*2+1][1] = r3;
                LDSM_X4(r0, r1, r2, r3, swz64(sBlo, brow, bcol));
                bl[g*2+0][0] = r0; bl[g*2+1][0] = r1;
                bl[g*2+0][1] = r2; bl[g*2+1][1] = r3;
            }
#pragma unroll
            for (int mt = 0; mt < 4; mt++) {
                int arow = warp_m*64 + mt*16 + (lane & 15);
                int acol = ks*32 + ((lane >> 4) << 4);
                uint32_t ah0, ah1, ah2, ah3, al0, al1, al2, al3;
                LDSM_X4(ah0, ah1, ah2, ah3, swz64(sAhi, arow, acol));
                LDSM_X4(al0, al1, al2, al3, swz64(sAlo, arow, acol));
#pragma unroll
                for (int nt = 0; nt < 4; nt++) {
                    MMA16816(acc[mt][nt], ah0, ah1, ah2, ah3, bh[nt][0], bh[nt][1]);
                    MMA16816(acc[mt][nt], ah0, ah1, ah2, ah3, bl[nt][0], bl[nt][1]);
                    MMA16816(acc[mt][nt], al0, al1, al2, al3, bh[nt][0], bh[nt][1]);
                }
            }
        }
    }

    const int gr = lane >> 2;
    const int gc = (lane & 3) * 2;
#pragma unroll
    for (int mt = 0; mt < 4; mt++) {
#pragma unroll
        for (int nt = 0; nt < 4; nt++) {
            int m0 = row0 + warp_m*64 + mt*16 + gr;
            int jg = col0 + warp_n*32 + nt*8 + gc;
            float b0 = bias[jg], b1 = bias[jg+1];
#pragma unroll
            for (int half = 0; half < 2; half++) {
                int m = m0 + half*8;
                float c0 = acc[mt][nt][half*2+0] + b0;
                float c1 = acc[mt][nt][half*2+1] + b1;
                if (MODE == 0) {
                    int which = col0 / DD;
                    int rem = jg - which * DD;
                    int h = rem >> 6, dd0 = rem & 63;
                    int bidx = m >> 10, n = m & 1023;
                    float sc = (which == 0) ? 0.125f : 1.0f;
                    c0 *= sc; c1 *= sc;
                    size_t off = (((size_t)(bidx*HH + h))*NN + n)*HD + dd0;
                    __nv_bfloat16* dh = (which == 0 ? g_qh : (which == 1 ? g_kh : g_vh)) + off;
                    __nv_bfloat16* dl = (which == 0 ? g_ql : (which == 1 ? g_kl : g_vl)) + off;
                    __nv_bfloat16 h0 = __float2bfloat16_rn(c0);
                    __nv_bfloat16 h1 = __float2bfloat16_rn(c1);
                    __nv_bfloat162 hh; hh.x = h0; hh.y = h1;
                    __nv_bfloat162 ll = __floats2bfloat162_rn(c0 - __bfloat162float(h0),
                                                              c1 - __bfloat162float(h1));
                    *(__nv_bfloat162*)dh = hh;
                    *(__nv_bfloat162*)dl = ll;
                } else {
                    *(float2*)(Cout + (size_t)m * DD + jg) = make_float2(c0, c1);
                }
            }
        }
    }
}

// ---------------- HMMA flash attention, cp.async 2-stage K/V pipeline ----------------
// BR=128 rows per CTA, BC=64 cols per tile, 8 warps (16 rows each).
#define A2_QH 0
#define A2_QL 16384
#define A2_KV 32768
#define KV_STAGE 32768     // KH 8K | KL 8K | VH 8K | VL 8K
#define A2_META (A2_KV + 2*KV_STAGE)   // 98304
#define ATTN2_SMEM (A2_META + (128+64)*4 + (128+128+64+64+257)*4)

__device__ __forceinline__ void attn_load_kv(uint32_t sbase, size_t kvbase, int c0, int tid) {
#pragma unroll
    for (int i = 0; i < 2; i++) {
        int c = i*256 + tid;          // 0..511
        int row = c >> 3, c16 = c & 7;
        uint32_t off = (uint32_t)(row*128 + c16*16);
        uint32_t sw = off ^ ((off >> 3) & 0x70);
        size_t g = kvbase + (size_t)(c0 + row)*HD + c16*8;
        CP_ASYNC16(sbase + sw,         g_kh + g);
        CP_ASYNC16(sbase + 8192 + sw,  g_kl + g);
        CP_ASYNC16(sbase + 16384 + sw, g_vh + g);
        CP_ASYNC16(sbase + 24576 + sw, g_vl + g);
    }
}

__global__ __launch_bounds__(256, 2) void attn_mma(const float* __restrict__ elev,
                                                   const float* __restrict__ btab,
                                                   const float* __restrict__ alpha_p) {
    extern __shared__ char sm[];
    uint32_t sb = smem_u32(sm);
    float* er  = (float*)(sm + A2_META);
    float* ec  = er + 128;
    int* cxr   = (int*)(ec + 64);
    int* cyr   = cxr + 128;
    int* cxc   = cyr + 128;
    int* cyc   = cxc + 64;
    int* lut   = cyc + 64;

    const int tid = threadIdx.x;
    const int wid = tid >> 5;
    const int lane = tid & 31;
    const int gr = lane >> 2;
    const int q2 = (lane & 3) * 2;
    const int r0 = blockIdx.x * 128;
    const int h  = blockIdx.y;
    const int b  = blockIdx.z;
    const float alpha = alpha_p[0];

    const size_t kvbase = ((size_t)(b*HH + h))*NN*HD;

    // prologue: first K/V tile in flight
    attn_load_kv(sb + A2_KV, kvbase, 0, tid);
    CP_COMMIT();

    // bucket LUT
    for (int i = tid; i < 257; i += 256) {
        int rel = i - 128;
        int neg = -rel;
        int ret = (neg < 0) ? 16 : 0;
        int a = (neg < 0) ? -neg : neg;
        int bv;
        if (a < 8) bv = a;
        else {
            float t = logf((float)a * 0.125f) / 2.7725887222397811f * 8.0f;
            bv = 8 + (int)t;
            if (bv > 15) bv = 15;
        }
        lut[i] = ret + bv;
    }

    // load Q (hi/lo) into smem + row metadata
    const size_t qbase = (((size_t)(b*HH + h))*NN + r0)*HD;
#pragma unroll
    for (int it = 0; it < 4; it++) {
        int idx = it*256 + tid;
        int row = idx >> 3;
        int cg  = idx & 7;
        uint32_t off = (uint32_t)(row*128 + cg*16);
        uint32_t sw = off ^ ((off >> 3) & 0x70);
        *(uint4*)(sm + A2_QH + sw) = *(const uint4*)(g_qh + qbase + (size_t)row*HD + cg*8);
        *(uint4*)(sm + A2_QL + sw) = *(const uint4*)(g_ql + qbase + (size_t)row*HD + cg*8);
    }
    if (tid < 128) {
        int gidx = b*NN + r0 + tid;
        cxr[tid] = g_cx[gidx]; cyr[tid] = g_cy[gidx]; er[tid] = elev[gidx];
    }

    float m_i[2], l_i[2], oacc[8][4];
#pragma unroll
    for (int rr = 0; rr < 2; rr++) { m_i[rr] = -INFINITY; l_i[rr] = 0.0f; }
#pragma unroll
    for (int dt = 0; dt < 8; dt++)
#pragma unroll
        for (int r = 0; r < 4; r++) oacc[dt][r] = 0.0f;

    for (int t = 0; t < NN/64; t++) {
        const int c0 = t*64;
        __syncthreads();   // protects stage (t+1)&1 (computed at t-1) and meta
        if (t + 1 < NN/64) {
            attn_load_kv(sb + A2_KV + ((t+1)&1)*KV_STAGE, kvbase, c0 + 64, tid);
            CP_COMMIT();
        }
        if (tid < 64) {
            int gidx = b*NN + c0 + tid;
            cxc[tid] = g_cx[gidx]; cyc[tid] = g_cy[gidx]; ec[tid] = elev[gidx];
        }
        if (t + 1 < NN/64) CP_WAIT(1); else CP_WAIT(0);
        __syncthreads();

        const uint32_t kvb = sb + A2_KV + (t&1)*KV_STAGE;

        // ---- S = Q K^T ----
        float sacc[8][4];
#pragma unroll
        for (int nt = 0; nt < 8; nt++)
#pragma unroll
            for (int r = 0; r < 4; r++) sacc[nt][r] = 0.0f;

#pragma unroll
        for (int ks = 0; ks < 4; ks++) {
            int arow = wid*16 + (lane & 15);
            int acol = ks*32 + ((lane >> 4) << 4);
            uint32_t ah0, ah1, ah2, ah3, al0, al1, al2, al3;
            LDSM_X4(ah0, ah1, ah2, ah3, swz(sb + A2_QH, arow, acol));
            LDSM_X4(al0, al1, al2, al3, swz(sb + A2_QL, arow, acol));
#pragma unroll
            for (int g = 0; g < 4; g++) {
                int brow = g*16 + (lane & 15);
                int bcol = ks*32 + ((lane >> 4) << 4);
                uint32_t kh0, kh1, kh2, kh3, kl0, kl1, kl2, kl3;
                LDSM_X4(kh0, kh1, kh2, kh3, swz(kvb, brow, bcol));
                LDSM_X4(kl0, kl1, kl2, kl3, swz(kvb + 8192, brow, bcol));
                MMA16816(sacc[g*2+0], ah0, ah1, ah2, ah3, kh0, kh2);
                MMA16816(sacc[g*2+0], ah0, ah1, ah2, ah3, kl0, kl2);
                MMA16816(sacc[g*2+0], al0, al1, al2, al3, kh0, kh2);
                MMA16816(sacc[g*2+1], ah0, ah1, ah2, ah3, kh1, kh3);
                MMA16816(sacc[g*2+1], ah0, ah1, ah2, ah3, kl1, kl3);
                MMA16816(sacc[g*2+1], al0, al1, al2, al3, kh1, kh3);
            }
        }

        // ---- biases + online softmax ----
#pragma unroll
        for (int rr = 0; rr < 2; rr++) {
            int lrow = wid*16 + gr + rr*8;
            int cxi = cxr[lrow], cyi = cyr[lrow];
            float ei = er[lrow];
            float rm = -INFINITY;
#pragma unroll
            for (int nt = 0; nt < 8; nt++) {
#pragma unroll
                for (int e = 0; e < 2; e++) {
                    int lc = nt*8 + q2 + e;
                    int bx = lut[cxi - cxc[lc] + 128];
                    int by = lut[cyi - cyc[lc] + 128];
                    float rb = __ldg(btab + (bx*32 + by)*HH + h);
                    float diff = (ec[lc] - ei) * 0.001f;
                    float eb = fminf(fmaxf(-alpha * fmaxf(diff, 0.0f), -10.0f), 0.0f);
                    float s = sacc[nt][rr*2 + e] + rb + eb;
                    sacc[nt][rr*2 + e] = s;
                    rm = fmaxf(rm, s);
                }
            }
            rm = fmaxf(rm, __shfl_xor_sync(0xffffffffu, rm, 1));
            rm = fmaxf(rm, __shfl_xor_sync(0xffffffffu, rm, 2));
            float mn = fmaxf(m_i[rr], rm);
            float corr = __expf(m_i[rr] - mn);
            m_i[rr] = mn;
            float rs = 0.0f;
#pragma unroll
            for (int nt = 0; nt < 8; nt++) {
#pragma unroll
                for (int e = 0; e < 2; e++) {
                    float p = __expf(sacc[nt][rr*2 + e] - mn);
                    sacc[nt][rr*2 + e] = p;
                    rs += p;
                }
            }
            rs += __shfl_xor_sync(0xffffffffu, rs, 1);
            rs += __shfl_xor_sync(0xffffffffu, rs, 2);
            l_i[rr] = l_i[rr] * corr + rs;
#pragma unroll
            for (int dt = 0; dt < 8; dt++) {
                oacc[dt][rr*2 + 0] *= corr;
                oacc[dt][rr*2 + 1] *= corr;
            }
        }

        // ---- O += P V ----
#pragma unroll
        for (int kc = 0; kc < 4; kc++) {
            uint32_t pah0 = pack_hi(sacc[2*kc][0],   sacc[2*kc][1]);
            uint32_t pah1 = pack_hi(sacc[2*kc][2],   sacc[2*kc][3]);
            uint32_t pah2 = pack_hi(sacc[2*kc+1][0], sacc[2*kc+1][1]);
            uint32_t pah3 = pack_hi(sacc[2*kc+1][2], sacc[2*kc+1][3]);
            uint32_t pal0 = pack_lo(sacc[2*kc][0],   sacc[2*kc][1]);
            uint32_t pal1 = pack_lo(sacc[2*kc][2],   sacc[2*kc][3]);
            uint32_t pal2 = pack_lo(sacc[2*kc+1][0], sacc[2*kc+1][1]);
            uint32_t pal3 = pack_lo(sacc[2*kc+1][2], sacc[2*kc+1][3]);
#pragma unroll
            for (int dp = 0; dp < 4; dp++) {
                int vrow = kc*16 + (lane & 15);
                int vcol = dp*32 + ((lane >> 4) << 4);
                uint32_t vh0, vh1, vh2, vh3, vl0, vl1, vl2, vl3;
                LDSM_X4_T(vh0, vh1, vh2, vh3, swz(kvb + 16384, vrow, vcol));
                LDSM_X4_T(vl0, vl1, vl2, vl3, swz(kvb + 24576, vrow, vcol));
                MMA16816(oacc[dp*2+0], pah0, pah1, pah2, pah3, vh0, vh1);
                MMA16816(oacc[dp*2+0], pah0, pah1, pah2, pah3, vl0, vl1);
                MMA16816(oacc[dp*2+0], pal0, pal1, pal2, pal3, vh0, vh1);
                MMA16816(oacc[dp*2+1], pah0, pah1, pah2, pah3, vh2, vh3);
                MMA16816(oacc[dp*2+1], pah0, pah1, pah2, pah3, vl2, vl3);
                MMA16816(oacc[dp*2+1], pal0, pal1, pal2, pal3, vh2, vh3);
            }
        }
    }

    // ---- normalize + write bf16 hi/lo att ----
#pragma unroll
    for (int rr = 0; rr < 2; rr++) {
        float inv = 1.0f / l_i[rr];
        int row = r0 + wid*16 + gr + rr*8;
#pragma unroll
        for (int dt = 0; dt < 8; dt++) {
            float o0 = oacc[dt][rr*2+0] * inv;
            float o1 = oacc[dt][rr*2+1] * inv;
            size_t idx = ((size_t)b*NN + row)*DD + h*HD + dt*8 + q2;
            uint32_t hh = pack_hi(o0, o1);
            uint32_t ll = pack_lo(o0, o1);
            *(uint32_t*)(g_atth + idx) = hh;
            *(uint32_t*)(g_attl + idx) = ll;
        }
    }
}

// ---------------- launcher ----------------
extern "C" void kernel_launch(void* const* d_in, const int* in_sizes, int n_in,
                              void* d_out, int out_size) {
    const float* x       = (const float*)d_in[0];
    const float* coords  = (const float*)d_in[1];
    const float* elev    = (const float*)d_in[2];
    const float* qkv_w   = (const float*)d_in[3];
    const float* qkv_b   = (const float*)d_in[4];
    const float* proj_w  = (const float*)d_in[5];
    const float* proj_b  = (const float*)d_in[6];
    const float* btab    = (const float*)d_in[7];
    const float* alpha   = (const float*)d_in[8];
    float* out = (float*)d_out;

    prep_kernel<<<(BB*NN + 255)/256, 256>>>(coords);

    __nv_bfloat16 *xh, *xl, *wqh, *wql, *wph, *wpl;
    cudaGetSymbolAddress((void**)&xh,  g_xh);
    cudaGetSymbolAddress((void**)&xl,  g_xl);
    cudaGetSymbolAddress((void**)&wqh, g_wqh);
    cudaGetSymbolAddress((void**)&wql, g_wql);
    cudaGetSymbolAddress((void**)&wph, g_wph);
    cudaGetSymbolAddress((void**)&wpl, g_wpl);
    __nv_bfloat16 *ath, *atl;
    cudaGetSymbolAddress((void**)&ath, g_atth);
    cudaGetSymbolAddress((void**)&atl, g_attl);

    split_kernel<<<(MROWS*KDIM/4 + 255)/256, 256>>>(x, xh, xl, MROWS*KDIM);
    split_kernel<<<(3*DD*KDIM/4 + 255)/256, 256>>>(qkv_w, wqh, wql, 3*DD*KDIM);
    split_kernel<<<(DD*KDIM/4 + 255)/256, 256>>>(proj_w, wph, wpl, DD*KDIM);

    cudaFuncSetAttribute(mma_gemm<0>, cudaFuncAttributeMaxDynamicSharedMemorySize, GEMM_SMEM);
    cudaFuncSetAttribute(mma_gemm<1>, cudaFuncAttributeMaxDynamicSharedMemorySize, GEMM_SMEM);
    cudaFuncSetAttribute(attn_mma, cudaFuncAttributeMaxDynamicSharedMemorySize, ATTN2_SMEM);

    mma_gemm<0><<<dim3((3*DD)/128, MROWS/128), 256, GEMM_SMEM>>>(xh, xl, wqh, wql, qkv_b, nullptr);

    attn_mma<<<dim3(NN/128, HH, BB), 256, ATTN2_SMEM>>>(elev, btab, alpha);

    mma_gemm<1><<<dim3(DD/128, MROWS/128), 256, GEMM_SMEM>>>(ath, atl, wph, wpl, proj_b, out);
}

// round 7
// speedup vs baseline: 1.1333x; 1.1333x over previous
#include <cuda_runtime.h>
#include <cuda_bf16.h>
#include <math.h>
#include <stdint.h>

#define BB 4
#define NN 1024
#define DD 768
#define HH 12
#define HD 64
#define MROWS (BB*NN)          // 4096
#define KDIM 768
#define KCHUNK 64
#define NCHUNKS (KDIM/KCHUNK)  // 12

// ---------------- scratch (no allocations allowed) ----------------
__device__ __nv_bfloat16 g_qh[BB*HH*NN*HD];
__device__ __nv_bfloat16 g_ql[BB*HH*NN*HD];
__device__ __nv_bfloat16 g_kh[BB*HH*NN*HD];
__device__ __nv_bfloat16 g_kl[BB*HH*NN*HD];
__device__ __nv_bfloat16 g_vh[BB*HH*NN*HD];
__device__ __nv_bfloat16 g_vl[BB*HH*NN*HD];
__device__ __nv_bfloat16 g_xh[MROWS*KDIM];
__device__ __nv_bfloat16 g_xl[MROWS*KDIM];
__device__ __nv_bfloat16 g_wqh[3*DD*KDIM];
__device__ __nv_bfloat16 g_wql[3*DD*KDIM];
__device__ __nv_bfloat16 g_wph[DD*KDIM];
__device__ __nv_bfloat16 g_wpl[DD*KDIM];
__device__ __nv_bfloat16 g_atth[BB*NN*DD];
__device__ __nv_bfloat16 g_attl[BB*NN*DD];
__device__ int   g_cx[BB*NN];
__device__ int   g_cy[BB*NN];

// ---------------- helpers ----------------
__device__ __forceinline__ uint32_t smem_u32(const void* p) {
    uint32_t a;
    asm("{ .reg .u64 t; cvta.to.shared.u64 t, %1; cvt.u32.u64 %0, t; }" : "=r"(a) : "l"(p));
    return a;
}

#define LDSM_X4(r0, r1, r2, r3, addr) \
    asm volatile("ldmatrix.sync.aligned.m8n8.x4.shared.b16 {%0,%1,%2,%3}, [%4];" \
        : "=r"(r0), "=r"(r1), "=r"(r2), "=r"(r3) : "r"(addr))

#define LDSM_X4_T(r0, r1, r2, r3, addr) \
    asm volatile("ldmatrix.sync.aligned.m8n8.x4.trans.shared.b16 {%0,%1,%2,%3}, [%4];" \
        : "=r"(r0), "=r"(r1), "=r"(r2), "=r"(r3) : "r"(addr))

#define MMA16816(d, a0, a1, a2, a3, b0, b1) \
    asm volatile("mma.sync.aligned.m16n8k16.row.col.f32.bf16.bf16.f32 " \
        "{%0,%1,%2,%3}, {%4,%5,%6,%7}, {%8,%9}, {%0,%1,%2,%3};" \
        : "+f"((d)[0]), "+f"((d)[1]), "+f"((d)[2]), "+f"((d)[3]) \
        : "r"(a0), "r"(a1), "r"(a2), "r"(a3), "r"(b0), "r"(b1))

#define CP_ASYNC16(dst, src) \
    asm volatile("cp.async.cg.shared.global [%0], [%1], 16;" :: "r"(dst), "l"(src) : "memory")
#define CP_COMMIT() asm volatile("cp.async.commit_group;" ::: "memory")
#define CP_WAIT(n)  asm volatile("cp.async.wait_group %0;" :: "n"(n) : "memory")

// SW128 swizzled address within a [rows][128 bytes] tile
__device__ __forceinline__ uint32_t swz(uint32_t base, int row, int colb) {
    uint32_t off = (uint32_t)(row * 128 + colb);
    return base + (off ^ ((off >> 3) & 0x70));
}

// fp32 -> bf16 hi/lo split of a float4 (packed as 2x bf16x2 each)
__device__ __forceinline__ void split4(float4 f, uint2& hi, uint2& lo) {
    __nv_bfloat16 hx = __float2bfloat16_rn(f.x);
    __nv_bfloat16 hy = __float2bfloat16_rn(f.y);
    __nv_bfloat16 hz = __float2bfloat16_rn(f.z);
    __nv_bfloat16 hw = __float2bfloat16_rn(f.w);
    __nv_bfloat162 h01; h01.x = hx; h01.y = hy;
    __nv_bfloat162 h23; h23.x = hz; h23.y = hw;
    hi.x = *(uint32_t*)&h01; hi.y = *(uint32_t*)&h23;
    __nv_bfloat162 l01 = __floats2bfloat162_rn(f.x - __bfloat162float(hx), f.y - __bfloat162float(hy));
    __nv_bfloat162 l23 = __floats2bfloat162_rn(f.z - __bfloat162float(hz), f.w - __bfloat162float(hw));
    lo.x = *(uint32_t*)&l01; lo.y = *(uint32_t*)&l23;
}

__device__ __forceinline__ uint32_t pack_hi(float a, float b) {
    __nv_bfloat162 h = __floats2bfloat162_rn(a, b);
    return *(uint32_t*)&h;
}
__device__ __forceinline__ uint32_t pack_lo(float a, float b) {
    __nv_bfloat16 ha = __float2bfloat16_rn(a);
    __nv_bfloat16 hb = __float2bfloat16_rn(b);
    __nv_bfloat162 l = __floats2bfloat162_rn(a - __bfloat162float(ha), b - __bfloat162float(hb));
    return *(uint32_t*)&l;
}

// ---------------- prep: integer grid coords ----------------
__global__ void prep_kernel(const float* __restrict__ coords) {
    int i = blockIdx.x * blockDim.x + threadIdx.x;
    if (i < BB*NN) {
        g_cx[i] = (int)(coords[2*i + 0] * 128.0f);
        g_cy[i] = (int)(coords[2*i + 1] * 128.0f);
    }
}

// ---------------- split: fp32 -> bf16 hi/lo ----------------
__global__ void split_kernel(const float* __restrict__ src,
                             __nv_bfloat16* __restrict__ h,
                             __nv_bfloat16* __restrict__ l, int n) {
    int i = (blockIdx.x * blockDim.x + threadIdx.x) * 4;
    if (i < n) {
        float4 f = *(const float4*)(src + i);
        uint2 hh, ll;
        split4(f, hh, ll);
        *(uint2*)(h + i) = hh;
        *(uint2*)(l + i) = ll;
    }
}

// ---------------- HMMA bf16x3 GEMM, 128x64 tile, KCHUNK=64, 2-stage, 2 CTAs/SM ----
// C[M,N] = A[M,K].B[N,K]^T + bias.  A,B pre-split bf16 hi/lo.
// stage: Ahi 16K | Alo 16K | Bhi 8K | Blo 8K = 48KB
#define GSTAGES 2
#define GS_AHI 0
#define GS_ALO 16384
#define GS_BHI 32768
#define GS_BLO 40960
#define GSTAGE_BYTES 49152
#define GEMM_SMEM (GSTAGES*GSTAGE_BYTES)    // 96KB -> 2 CTAs/SM

__device__ __forceinline__ void gemm_load_stage(uint32_t sbase,
    const __nv_bfloat16* __restrict__ Ah, const __nv_bfloat16* __restrict__ Al,
    const __nv_bfloat16* __restrict__ Bh, const __nv_bfloat16* __restrict__ Bl,
    int row0, int col0, int kt0, int tid) {
    // A: 128 rows x 8 chunks of 16B
#pragma unroll
    for (int i = 0; i < 4; i++) {
        int c = i*256 + tid;
        int row = c >> 3, cg = c & 7;
        uint32_t off = (uint32_t)(row*128 + cg*16);
        uint32_t sw = off ^ ((off >> 3) & 0x70);
        size_t ga = (size_t)(row0 + row)*KDIM + kt0 + cg*8;
        CP_ASYNC16(sbase + GS_AHI + sw, Ah + ga);
        CP_ASYNC16(sbase + GS_ALO + sw, Al + ga);
    }
    // B: 64 rows x 8 chunks of 16B
#pragma unroll
    for (int i = 0; i < 2; i++) {
        int c = i*256 + tid;
        int row = c >> 3, cg = c & 7;
        uint32_t off = (uint32_t)(row*128 + cg*16);
        uint32_t sw = off ^ ((off >> 3) & 0x70);
        size_t gb = (size_t)(col0 + row)*KDIM + kt0 + cg*8;
        CP_ASYNC16(sbase + GS_BHI + sw, Bh + gb);
        CP_ASYNC16(sbase + GS_BLO + sw, Bl + gb);
    }
}

template<int MODE>
__global__ __launch_bounds__(256, 2) void mma_gemm(
        const __nv_bfloat16* __restrict__ Ah, const __nv_bfloat16* __restrict__ Al,
        const __nv_bfloat16* __restrict__ Bh, const __nv_bfloat16* __restrict__ Bl,
        const float* __restrict__ bias, float* __restrict__ Cout) {
    extern __shared__ char smem[];
    uint32_t sb = smem_u32(smem);

    const int tid = threadIdx.x;
    const int wid = tid >> 5;
    const int lane = tid & 31;
    const int warp_m = wid & 3;       // 4 warps x 32 rows
    const int warp_n = wid >> 2;      // 2 warps x 32 cols
    const int row0 = blockIdx.y * 128;
    const int col0 = blockIdx.x * 64;

    float acc[2][4][4];
#pragma unroll
    for (int i = 0; i < 2; i++)
#pragma unroll
        for (int j = 0; j < 4; j++)
#pragma unroll
            for (int r = 0; r < 4; r++) acc[i][j][r] = 0.0f;

    gemm_load_stage(sb, Ah, Al, Bh, Bl, row0, col0, 0, tid);
    CP_COMMIT();

    for (int ch = 0; ch < NCHUNKS; ch++) {
        __syncthreads();   // all warps done computing chunk ch-1 (buffer (ch+1)&1 free)
        if (ch + 1 < NCHUNKS) {
            gemm_load_stage(sb + ((ch+1)&1)*GSTAGE_BYTES, Ah, Al, Bh, Bl,
                            row0, col0, (ch+1)*KCHUNK, tid);
            CP_COMMIT();
            CP_WAIT(1);
        } else {
            CP_WAIT(0);
        }
        __syncthreads();   // stage ch visible to all

        const uint32_t st = sb + (ch & 1)*GSTAGE_BYTES;
#pragma unroll
        for (int ks = 0; ks < 4; ks++) {
            // B frags: warp's 32 cols, this k16
            uint32_t bh[4][2], bl[4][2];
#pragma unroll
            for (int g = 0; g < 2; g++) {
                int brow = warp_n*32 + g*16 + (lane & 15);
                int bcol = ks*32 + ((lane >> 4) << 4);
                uint32_t r0, r1, r2, r3;
                LDSM_X4(r0, r1, r2, r3, swz(st + GS_BHI, brow, bcol));
                bh[g*2+0][0] = r0; bh[g*2+1][0] = r1;
                bh[g*2+0][1] = r2; bh[g*2+1][1] = r3;
                LDSM_X4(r0, r1, r2, r3, swz(st + GS_BLO, brow, bcol));
                bl[g*2+0][0] = r0; bl[g*2+1][0] = r1;
                bl[g*2+0][1] = r2; bl[g*2+1][1] = r3;
            }
#pragma unroll
            for (int mt = 0; mt < 2; mt++) {
                int arow = warp_m*32 + mt*16 + (lane & 15);
                int acol = ks*32 + ((lane >> 4) << 4);
                uint32_t ah0, ah1, ah2, ah3, al0, al1, al2, al3;
                LDSM_X4(ah0, ah1, ah2, ah3, swz(st + GS_AHI, arow, acol));
                LDSM_X4(al0, al1, al2, al3, swz(st + GS_ALO, arow, acol));
#pragma unroll
                for (int nt = 0; nt < 4; nt++) {
                    MMA16816(acc[mt][nt], ah0, ah1, ah2, ah3, bh[nt][0], bh[nt][1]);
                    MMA16816(acc[mt][nt], ah0, ah1, ah2, ah3, bl[nt][0], bl[nt][1]);
                    MMA16816(acc[mt][nt], al0, al1, al2, al3, bh[nt][0], bh[nt][1]);
                }
            }
        }
    }

    const int gr = lane >> 2;
    const int gc = (lane & 3) * 2;
#pragma unroll
    for (int mt = 0; mt < 2; mt++) {
#pragma unroll
        for (int nt = 0; nt < 4; nt++) {
            int m0 = row0 + warp_m*32 + mt*16 + gr;
            int jg = col0 + warp_n*32 + nt*8 + gc;
            float b0 = bias[jg], b1 = bias[jg+1];
#pragma unroll
            for (int half = 0; half < 2; half++) {
                int m = m0 + half*8;
                float c0 = acc[mt][nt][half*2+0] + b0;
                float c1 = acc[mt][nt][half*2+1] + b1;
                if (MODE == 0) {
                    int which = jg / DD;
                    int rem = jg - which * DD;
                    int h = rem >> 6, dd0 = rem & 63;
                    int bidx = m >> 10, n = m & 1023;
                    float sc = (which == 0) ? 0.125f : 1.0f;
                    c0 *= sc; c1 *= sc;
                    size_t off = (((size_t)(bidx*HH + h))*NN + n)*HD + dd0;
                    __nv_bfloat16* dh = (which == 0 ? g_qh : (which == 1 ? g_kh : g_vh)) + off;
                    __nv_bfloat16* dl = (which == 0 ? g_ql : (which == 1 ? g_kl : g_vl)) + off;
                    __nv_bfloat16 h0 = __float2bfloat16_rn(c0);
                    __nv_bfloat16 h1 = __float2bfloat16_rn(c1);
                    __nv_bfloat162 hh; hh.x = h0; hh.y = h1;
                    __nv_bfloat162 ll = __floats2bfloat162_rn(c0 - __bfloat162float(h0),
                                                              c1 - __bfloat162float(h1));
                    *(__nv_bfloat162*)dh = hh;
                    *(__nv_bfloat162*)dl = ll;
                } else {
                    *(float2*)(Cout + (size_t)m * DD + jg) = make_float2(c0, c1);
                }
            }
        }
    }
}

// ---------------- HMMA flash attention, cp.async 2-stage K/V pipeline (R5 config) ----
#define A2_QH 0
#define A2_QL 16384
#define A2_KV 32768
#define KV_STAGE 32768     // KH 8K | KL 8K | VH 8K | VL 8K
#define A2_META (A2_KV + 2*KV_STAGE)   // 98304
#define ATTN2_SMEM (A2_META + (128+64)*4 + (128+128+64+64+257)*4)

__device__ __forceinline__ void attn_load_kv(uint32_t sbase, size_t kvbase, int c0, int tid) {
#pragma unroll
    for (int i = 0; i < 2; i++) {
        int c = i*256 + tid;          // 0..511
        int row = c >> 3, c16 = c & 7;
        uint32_t off = (uint32_t)(row*128 + c16*16);
        uint32_t sw = off ^ ((off >> 3) & 0x70);
        size_t g = kvbase + (size_t)(c0 + row)*HD + c16*8;
        CP_ASYNC16(sbase + sw,         g_kh + g);
        CP_ASYNC16(sbase + 8192 + sw,  g_kl + g);
        CP_ASYNC16(sbase + 16384 + sw, g_vh + g);
        CP_ASYNC16(sbase + 24576 + sw, g_vl + g);
    }
}

__global__ __launch_bounds__(256) void attn_mma(const float* __restrict__ elev,
                                                const float* __restrict__ btab,
                                                const float* __restrict__ alpha_p) {
    extern __shared__ char sm[];
    uint32_t sb = smem_u32(sm);
    float* er  = (float*)(sm + A2_META);
    float* ec  = er + 128;
    int* cxr   = (int*)(ec + 64);
    int* cyr   = cxr + 128;
    int* cxc   = cyr + 128;
    int* cyc   = cxc + 64;
    int* lut   = cyc + 64;

    const int tid = threadIdx.x;
    const int wid = tid >> 5;
    const int lane = tid & 31;
    const int gr = lane >> 2;
    const int q2 = (lane & 3) * 2;
    const int r0 = blockIdx.x * 128;
    const int h  = blockIdx.y;
    const int b  = blockIdx.z;
    const float alpha = alpha_p[0];

    const size_t kvbase = ((size_t)(b*HH + h))*NN*HD;

    attn_load_kv(sb + A2_KV, kvbase, 0, tid);
    CP_COMMIT();

    for (int i = tid; i < 257; i += 256) {
        int rel = i - 128;
        int neg = -rel;
        int ret = (neg < 0) ? 16 : 0;
        int a = (neg < 0) ? -neg : neg;
        int bv;
        if (a < 8) bv = a;
        else {
            float t = logf((float)a * 0.125f) / 2.7725887222397811f * 8.0f;
            bv = 8 + (int)t;
            if (bv > 15) bv = 15;
        }
        lut[i] = ret + bv;
    }

    const size_t qbase = (((size_t)(b*HH + h))*NN + r0)*HD;
#pragma unroll
    for (int it = 0; it < 4; it++) {
        int idx = it*256 + tid;
        int row = idx >> 3;
        int cg  = idx & 7;
        uint32_t off = (uint32_t)(row*128 + cg*16);
        uint32_t sw = off ^ ((off >> 3) & 0x70);
        *(uint4*)(sm + A2_QH + sw) = *(const uint4*)(g_qh + qbase + (size_t)row*HD + cg*8);
        *(uint4*)(sm + A2_QL + sw) = *(const uint4*)(g_ql + qbase + (size_t)row*HD + cg*8);
    }
    if (tid < 128) {
        int gidx = b*NN + r0 + tid;
        cxr[tid] = g_cx[gidx]; cyr[tid] = g_cy[gidx]; er[tid] = elev[gidx];
    }

    float m_i[2], l_i[2], oacc[8][4];
#pragma unroll
    for (int rr = 0; rr < 2; rr++) { m_i[rr] = -INFINITY; l_i[rr] = 0.0f; }
#pragma unroll
    for (int dt = 0; dt < 8; dt++)
#pragma unroll
        for (int r = 0; r < 4; r++) oacc[dt][r] = 0.0f;

    for (int t = 0; t < NN/64; t++) {
        const int c0 = t*64;
        __syncthreads();
        if (t + 1 < NN/64) {
            attn_load_kv(sb + A2_KV + ((t+1)&1)*KV_STAGE, kvbase, c0 + 64, tid);
            CP_COMMIT();
        }
        if (tid < 64) {
            int gidx = b*NN + c0 + tid;
            cxc[tid] = g_cx[gidx]; cyc[tid] = g_cy[gidx]; ec[tid] = elev[gidx];
        }
        if (t + 1 < NN/64) CP_WAIT(1); else CP_WAIT(0);
        __syncthreads();

        const uint32_t kvb = sb + A2_KV + (t&1)*KV_STAGE;

        float sacc[8][4];
#pragma unroll
        for (int nt = 0; nt < 8; nt++)
#pragma unroll
            for (int r = 0; r < 4; r++) sacc[nt][r] = 0.0f;

#pragma unroll
        for (int ks = 0; ks < 4; ks++) {
            int arow = wid*16 + (lane & 15);
            int acol = ks*32 + ((lane >> 4) << 4);
            uint32_t ah0, ah1, ah2, ah3, al0, al1, al2, al3;
            LDSM_X4(ah0, ah1, ah2, ah3, swz(sb + A2_QH, arow, acol));
            LDSM_X4(al0, al1, al2, al3, swz(sb + A2_QL, arow, acol));
#pragma unroll
            for (int g = 0; g < 4; g++) {
                int brow = g*16 + (lane & 15);
                int bcol = ks*32 + ((lane >> 4) << 4);
                uint32_t kh0, kh1, kh2, kh3, kl0, kl1, kl2, kl3;
                LDSM_X4(kh0, kh1, kh2, kh3, swz(kvb, brow, bcol));
                LDSM_X4(kl0, kl1, kl2, kl3, swz(kvb + 8192, brow, bcol));
                MMA16816(sacc[g*2+0], ah0, ah1, ah2, ah3, kh0, kh2);
                MMA16816(sacc[g*2+0], ah0, ah1, ah2, ah3, kl0, kl2);
                MMA16816(sacc[g*2+0], al0, al1, al2, al3, kh0, kh2);
                MMA16816(sacc[g*2+1], ah0, ah1, ah2, ah3, kh1, kh3);
                MMA16816(sacc[g*2+1], ah0, ah1, ah2, ah3, kl1, kl3);
                MMA16816(sacc[g*2+1], al0, al1, al2, al3, kh1, kh3);
            }
        }

#pragma unroll
        for (int rr = 0; rr < 2; rr++) {
            int lrow = wid*16 + gr + rr*8;
            int cxi = cxr[lrow], cyi = cyr[lrow];
            float ei = er[lrow];
            float rm = -INFINITY;
#pragma unroll
            for (int nt = 0; nt < 8; nt++) {
#pragma unroll
                for (int e = 0; e < 2; e++) {
                    int lc = nt*8 + q2 + e;
                    int bx = lut[cxi - cxc[lc] + 128];
                    int by = lut[cyi - cyc[lc] + 128];
                    float rb = __ldg(btab + (bx*32 + by)*HH + h);
                    float diff = (ec[lc] - ei) * 0.001f;
                    float eb = fminf(fmaxf(-alpha * fmaxf(diff, 0.0f), -10.0f), 0.0f);
                    float s = sacc[nt][rr*2 + e] + rb + eb;
                    sacc[nt][rr*2 + e] = s;
                    rm = fmaxf(rm, s);
                }
            }
            rm = fmaxf(rm, __shfl_xor_sync(0xffffffffu, rm, 1));
            rm = fmaxf(rm, __shfl_xor_sync(0xffffffffu, rm, 2));
            float mn = fmaxf(m_i[rr], rm);
            float corr = __expf(m_i[rr] - mn);
            m_i[rr] = mn;
            float rs = 0.0f;
#pragma unroll
            for (int nt = 0; nt < 8; nt++) {
#pragma unroll
                for (int e = 0; e < 2; e++) {
                    float p = __expf(sacc[nt][rr*2 + e] - mn);
                    sacc[nt][rr*2 + e] = p;
                    rs += p;
                }
            }
            rs += __shfl_xor_sync(0xffffffffu, rs, 1);
            rs += __shfl_xor_sync(0xffffffffu, rs, 2);
            l_i[rr] = l_i[rr] * corr + rs;
#pragma unroll
            for (int dt = 0; dt < 8; dt++) {
                oacc[dt][rr*2 + 0] *= corr;
                oacc[dt][rr*2 + 1] *= corr;
            }
        }

#pragma unroll
        for (int kc = 0; kc < 4; kc++) {
            uint32_t pah0 = pack_hi(sacc[2*kc][0],   sacc[2*kc][1]);
            uint32_t pah1 = pack_hi(sacc[2*kc][2],   sacc[2*kc][3]);
            uint32_t pah2 = pack_hi(sacc[2*kc+1][0], sacc[2*kc+1][1]);
            uint32_t pah3 = pack_hi(sacc[2*kc+1][2], sacc[2*kc+1][3]);
            uint32_t pal0 = pack_lo(sacc[2*kc][0],   sacc[2*kc][1]);
            uint32_t pal1 = pack_lo(sacc[2*kc][2],   sacc[2*kc][3]);
            uint32_t pal2 = pack_lo(sacc[2*kc+1][0], sacc[2*kc+1][1]);
            uint32_t pal3 = pack_lo(sacc[2*kc+1][2], sacc[2*kc+1][3]);
#pragma unroll
            for (int dp = 0; dp < 4; dp++) {
                int vrow = kc*16 + (lane & 15);
                int vcol = dp*32 + ((lane >> 4) << 4);
                uint32_t vh0, vh1, vh2, vh3, vl0, vl1, vl2, vl3;
                LDSM_X4_T(vh0, vh1, vh2, vh3, swz(kvb + 16384, vrow, vcol));
                LDSM_X4_T(vl0, vl1, vl2, vl3, swz(kvb + 24576, vrow, vcol));
                MMA16816(oacc[dp*2+0], pah0, pah1, pah2, pah3, vh0, vh1);
                MMA16816(oacc[dp*2+0], pah0, pah1, pah2, pah3, vl0, vl1);
                MMA16816(oacc[dp*2+0], pal0, pal1, pal2, pal3, vh0, vh1);
                MMA16816(oacc[dp*2+1], pah0, pah1, pah2, pah3, vh2, vh3);
                MMA16816(oacc[dp*2+1], pah0, pah1, pah2, pah3, vl2, vl3);
                MMA16816(oacc[dp*2+1], pal0, pal1, pal2, pal3, vh2, vh3);
            }
        }
    }

#pragma unroll
    for (int rr = 0; rr < 2; rr++) {
        float inv = 1.0f / l_i[rr];
        int row = r0 + wid*16 + gr + rr*8;
#pragma unroll
        for (int dt = 0; dt < 8; dt++) {
            float o0 = oacc[dt][rr*2+0] * inv;
            float o1 = oacc[dt][rr*2+1] * inv;
            size_t idx = ((size_t)b*NN + row)*DD + h*HD + dt*8 + q2;
            uint32_t hh = pack_hi(o0, o1);
            uint32_t ll = pack_lo(o0, o1);
            *(uint32_t*)(g_atth + idx) = hh;
            *(uint32_t*)(g_attl + idx) = ll;
        }
    }
}

// ---------------- launcher ----------------
extern "C" void kernel_launch(void* const* d_in, const int* in_sizes, int n_in,
                              void* d_out, int out_size) {
    const float* x       = (const float*)d_in[0];
    const float* coords  = (const float*)d_in[1];
    const float* elev    = (const float*)d_in[2];
    const float* qkv_w   = (const float*)d_in[3];
    const float* qkv_b   = (const float*)d_in[4];
    const float* proj_w  = (const float*)d_in[5];
    const float* proj_b  = (const float*)d_in[6];
    const float* btab    = (const float*)d_in[7];
    const float* alpha   = (const float*)d_in[8];
    float* out = (float*)d_out;

    prep_kernel<<<(BB*NN + 255)/256, 256>>>(coords);

    __nv_bfloat16 *xh, *xl, *wqh, *wql, *wph, *wpl;
    cudaGetSymbolAddress((void**)&xh,  g_xh);
    cudaGetSymbolAddress((void**)&xl,  g_xl);
    cudaGetSymbolAddress((void**)&wqh, g_wqh);
    cudaGetSymbolAddress((void**)&wql, g_wql);
    cudaGetSymbolAddress((void**)&wph, g_wph);
    cudaGetSymbolAddress((void**)&wpl, g_wpl);
    __nv_bfloat16 *ath, *atl;
    cudaGetSymbolAddress((void**)&ath, g_atth);
    cudaGetSymbolAddress((void**)&atl, g_attl);

    split_kernel<<<(MROWS*KDIM/4 + 255)/256, 256>>>(x, xh, xl, MROWS*KDIM);
    split_kernel<<<(3*DD*KDIM/4 + 255)/256, 256>>>(qkv_w, wqh, wql, 3*DD*KDIM);
    split_kernel<<<(DD*KDIM/4 + 255)/256, 256>>>(proj_w, wph, wpl, DD*KDIM);

    cudaFuncSetAttribute(mma_gemm<0>, cudaFuncAttributeMaxDynamicSharedMemorySize, GEMM_SMEM);
    cudaFuncSetAttribute(mma_gemm<1>, cudaFuncAttributeMaxDynamicSharedMemorySize, GEMM_SMEM);
    cudaFuncSetAttribute(attn_mma, cudaFuncAttributeMaxDynamicSharedMemorySize, ATTN2_SMEM);

    mma_gemm<0><<<dim3((3*DD)/64, MROWS/128), 256, GEMM_SMEM>>>(xh, xl, wqh, wql, qkv_b, nullptr);

    attn_mma<<<dim3(NN/128, HH, BB), 256, ATTN2_SMEM>>>(elev, btab, alpha);

    mma_gemm<1><<<dim3(DD/64, MROWS/128), 256, GEMM_SMEM>>>(ath, atl, wph, wpl, proj_b, out);
}